// round 2
// baseline (speedup 1.0000x reference)
#include <cuda_runtime.h>
#include <cstdint>

#define B_  2
#define T_  2048
#define D_  1024
#define H_  16
#define DH_ 64
#define SCALE 0.125f   // 1/sqrt(64)

// Scratch (device globals: allocation-free, graph-capture safe)
__device__ float g_Q[B_*H_*T_*DH_];   // [B,H,T,DH]
__device__ float g_K[B_*H_*T_*DH_];
__device__ float g_V[B_*H_*T_*DH_];
__device__ float g_A[B_*T_*D_];       // attention output, head-concat layout [B,T,D]

__device__ __forceinline__ float neg_inf() { return __int_as_float(0xff800000u); }

// ----------------------------------------------------------------------------
// Kernel 1: per-head QKV projection.
// grid: (T/128, H, B*3)   z = b*3 + m (m: 0=Q,1=K,2=V).  block: 128 threads.
// Each thread computes one t-row: out[e] = bias[e] + sum_d x[d]*W[d][e]
// ----------------------------------------------------------------------------
__global__ __launch_bounds__(128) void qkv_kernel(
    const float* __restrict__ x,
    const float* __restrict__ Wq, const float* __restrict__ bq,
    const float* __restrict__ Wk, const float* __restrict__ bk,
    const float* __restrict__ Wv, const float* __restrict__ bv)
{
    __shared__ __align__(16) float Wsh[DH_*DH_];   // 16 KB
    __shared__ float xsh[DH_*128];                 // 32 KB (transposed: [d][tid])

    const int h = blockIdx.y;
    const int m = blockIdx.z % 3;
    const int b = blockIdx.z / 3;
    const float* W; const float* bias; float* outp;
    if (m == 0)      { W = Wq; bias = bq; outp = g_Q; }
    else if (m == 1) { W = Wk; bias = bk; outp = g_K; }
    else             { W = Wv; bias = bv; outp = g_V; }
    W += h*DH_*DH_; bias += h*DH_;

    const int tid = threadIdx.x;
    // Load W tile [64][64] into shared (2 threads per row)
    {
        int r = tid >> 1, half = tid & 1;
        const float4* src = (const float4*)(W + r*DH_ + half*32);
        float4* dst = (float4*)(Wsh + r*DH_ + half*32);
        #pragma unroll
        for (int i = 0; i < 8; i++) dst[i] = src[i];
    }
    // Load this thread's x row into transposed shared (conflict-free reads later)
    const int t = blockIdx.x*128 + tid;
    const float* xr = x + ((size_t)b*T_ + t)*D_ + h*DH_;
    #pragma unroll
    for (int i = 0; i < 16; i++) {
        float4 v = ((const float4*)xr)[i];
        xsh[(4*i+0)*128 + tid] = v.x;
        xsh[(4*i+1)*128 + tid] = v.y;
        xsh[(4*i+2)*128 + tid] = v.z;
        xsh[(4*i+3)*128 + tid] = v.w;
    }
    __syncthreads();

    float acc[DH_];
    #pragma unroll
    for (int e = 0; e < DH_; e++) acc[e] = bias[e];

    #pragma unroll 4
    for (int d = 0; d < DH_; d++) {
        float xd = xsh[d*128 + tid];
        #pragma unroll
        for (int e4 = 0; e4 < 16; e4++) {
            float4 w = ((const float4*)(Wsh + d*DH_))[e4];
            acc[4*e4+0] += xd*w.x;
            acc[4*e4+1] += xd*w.y;
            acc[4*e4+2] += xd*w.z;
            acc[4*e4+3] += xd*w.w;
        }
    }

    float* op = outp + (((size_t)b*H_ + h)*T_ + t)*DH_;
    #pragma unroll
    for (int e4 = 0; e4 < 16; e4++) {
        float4 v = make_float4(acc[4*e4], acc[4*e4+1], acc[4*e4+2], acc[4*e4+3]);
        ((float4*)op)[e4] = v;
    }
}

// ----------------------------------------------------------------------------
// Kernel 2: causal flash attention, fp32.
// grid: (T/128, H, B).  block: 128 threads, one q-row per thread.
// K/V tiles of 64 rows staged in shared; scores processed in chunks of 16
// (register arrays only touched with compile-time indices).
// ----------------------------------------------------------------------------
__global__ __launch_bounds__(128) void attn_kernel()
{
    __shared__ __align__(16) float Ksh[64*64];   // 16 KB
    __shared__ __align__(16) float Vsh[64*64];   // 16 KB

    const int h = blockIdx.y, b = blockIdx.z;
    const int tid = threadIdx.x;
    const int q = blockIdx.x*128 + tid;

    const float* Qp = g_Q + (((size_t)b*H_ + h)*T_ + q)*DH_;
    const float* Kb = g_K + (((size_t)b*H_ + h)*T_)*DH_;
    const float* Vb = g_V + (((size_t)b*H_ + h)*T_)*DH_;

    float qv[64];
    #pragma unroll
    for (int i = 0; i < 16; i++) {
        float4 v = ((const float4*)Qp)[i];
        qv[4*i]=v.x; qv[4*i+1]=v.y; qv[4*i+2]=v.z; qv[4*i+3]=v.w;
    }
    float o[64];
    #pragma unroll
    for (int e = 0; e < 64; e++) o[e] = 0.f;
    float mrow = neg_inf(), l = 0.f;

    const int nkt = blockIdx.x*2 + 2;       // k-tiles covering causal extent of block
    const int r = tid >> 1, half = tid & 1;

    for (int kt = 0; kt < nkt; kt++) {
        __syncthreads();
        const float4* ks = (const float4*)(Kb + ((size_t)(kt*64 + r))*64 + half*32);
        const float4* vs = (const float4*)(Vb + ((size_t)(kt*64 + r))*64 + half*32);
        float4* kd = (float4*)(Ksh + r*64 + half*32);
        float4* vd = (float4*)(Vsh + r*64 + half*32);
        #pragma unroll
        for (int i = 0; i < 8; i++) { kd[i] = ks[i]; vd[i] = vs[i]; }
        __syncthreads();

        const int kg0 = kt*64;
        #pragma unroll 1
        for (int jc = 0; jc < 64; jc += 16) {
            float s16[16];
            // S = q . K^T for 16 keys
            #pragma unroll
            for (int jj = 0; jj < 16; jj++) {
                const float* kr = Ksh + (jc+jj)*64;
                float a0=0.f, a1=0.f, a2=0.f, a3=0.f;
                #pragma unroll
                for (int e4 = 0; e4 < 16; e4++) {
                    float4 k = ((const float4*)kr)[e4];
                    a0 += qv[4*e4+0]*k.x;
                    a1 += qv[4*e4+1]*k.y;
                    a2 += qv[4*e4+2]*k.z;
                    a3 += qv[4*e4+3]*k.w;
                }
                s16[jj] = (a0+a1)+(a2+a3);
            }
            // scale + causal mask + chunk max
            float mt = neg_inf();
            #pragma unroll
            for (int jj = 0; jj < 16; jj++) {
                float sv = s16[jj]*SCALE;
                if (kg0 + jc + jj > q) sv = neg_inf();
                s16[jj] = sv;
                mt = fmaxf(mt, sv);
            }
            float mn = fmaxf(mrow, mt);      // finite after first chunk (k=0<=q always)
            float corr = __expf(mrow - mn);
            float ps = 0.f;
            #pragma unroll
            for (int jj = 0; jj < 16; jj++) {
                float p = __expf(s16[jj] - mn);
                s16[jj] = p;
                ps += p;
            }
            l = l*corr + ps;
            #pragma unroll
            for (int e = 0; e < 64; e++) o[e] *= corr;
            // O += P V
            #pragma unroll
            for (int jj = 0; jj < 16; jj++) {
                float p = s16[jj];
                const float* vr = Vsh + (jc+jj)*64;
                #pragma unroll
                for (int e4 = 0; e4 < 16; e4++) {
                    float4 v = ((const float4*)vr)[e4];
                    o[4*e4+0] += p*v.x;
                    o[4*e4+1] += p*v.y;
                    o[4*e4+2] += p*v.z;
                    o[4*e4+3] += p*v.w;
                }
            }
            mrow = mn;
        }
    }

    float inv = 1.f / l;
    float* op = g_A + ((size_t)b*T_ + q)*D_ + h*DH_;   // head-concat layout
    #pragma unroll
    for (int e4 = 0; e4 < 16; e4++) {
        float4 v = make_float4(o[4*e4]*inv, o[4*e4+1]*inv, o[4*e4+2]*inv, o[4*e4+3]*inv);
        ((float4*)op)[e4] = v;
    }
}

// ----------------------------------------------------------------------------
// Kernel 3: output projection  out = g_A @ Wo + bo
// grid: (B*T/128, D/64).  block: 128 threads, one output row per thread,
// 64-column block; K loop in chunks of 64.
// ----------------------------------------------------------------------------
__global__ __launch_bounds__(128) void oproj_kernel(
    const float* __restrict__ Wo, const float* __restrict__ bo,
    float* __restrict__ out)
{
    __shared__ __align__(16) float Wsh[64*64];   // 16 KB
    __shared__ float xsh[64*128];                // 32 KB (transposed)

    const int tid = threadIdx.x;
    const int row = blockIdx.x*128 + tid;        // flattened b*T + t
    const int n0 = blockIdx.y*64;

    float acc[64];
    #pragma unroll
    for (int e = 0; e < 64; e++) acc[e] = bo[n0 + e];

    const int r = tid >> 1, half = tid & 1;
    for (int k0 = 0; k0 < D_; k0 += 64) {
        __syncthreads();
        // Wo[k0+r][n0 + half*32 ...]
        const float4* ws = (const float4*)(Wo + (size_t)(k0 + r)*D_ + n0 + half*32);
        float4* wd = (float4*)(Wsh + r*64 + half*32);
        #pragma unroll
        for (int i = 0; i < 8; i++) wd[i] = ws[i];
        // x chunk for this thread's row, transposed into shared
        const float* xr = g_A + (size_t)row*D_ + k0;
        #pragma unroll
        for (int i = 0; i < 16; i++) {
            float4 v = ((const float4*)xr)[i];
            xsh[(4*i+0)*128 + tid] = v.x;
            xsh[(4*i+1)*128 + tid] = v.y;
            xsh[(4*i+2)*128 + tid] = v.z;
            xsh[(4*i+3)*128 + tid] = v.w;
        }
        __syncthreads();

        #pragma unroll 4
        for (int d = 0; d < 64; d++) {
            float xd = xsh[d*128 + tid];
            #pragma unroll
            for (int e4 = 0; e4 < 16; e4++) {
                float4 w = ((const float4*)(Wsh + d*64))[e4];
                acc[4*e4+0] += xd*w.x;
                acc[4*e4+1] += xd*w.y;
                acc[4*e4+2] += xd*w.z;
                acc[4*e4+3] += xd*w.w;
            }
        }
    }

    float* op = out + (size_t)row*D_ + n0;
    #pragma unroll
    for (int e4 = 0; e4 < 16; e4++) {
        float4 v = make_float4(acc[4*e4], acc[4*e4+1], acc[4*e4+2], acc[4*e4+3]);
        ((float4*)op)[e4] = v;
    }
}

// ----------------------------------------------------------------------------
extern "C" void kernel_launch(void* const* d_in, const int* in_sizes, int n_in,
                              void* d_out, int out_size)
{
    const float* x  = (const float*)d_in[0];
    const float* Wq = (const float*)d_in[1];
    const float* bq = (const float*)d_in[2];
    const float* Wk = (const float*)d_in[3];
    const float* bk = (const float*)d_in[4];
    const float* Wv = (const float*)d_in[5];
    const float* bv = (const float*)d_in[6];
    const float* Wo = (const float*)d_in[7];
    const float* bo = (const float*)d_in[8];
    float* out = (float*)d_out;

    qkv_kernel<<<dim3(T_/128, H_, B_*3), 128>>>(x, Wq, bq, Wk, bk, Wv, bv);
    attn_kernel<<<dim3(T_/128, H_, B_), 128>>>();
    oproj_kernel<<<dim3((B_*T_)/128, D_/64), 128>>>(Wo, bo, out);
}